// round 5
// baseline (speedup 1.0000x reference)
#include <cuda_runtime.h>
#include <cstdint>

#define N_USERS  40000
#define NTOT     100000
#define IN_DIM   128
#define HID      256
#define OUT_DIM  256
#define N_EDGES  600000

#define BSHIFT   6
#define BROWS    64
#define NBUCK    ((NTOT + 63) >> BSHIFT)   // 1563
#define SCAN_N   2048

// Scratch (allocation-free rule: device globals)
__device__ float g_x  [(size_t)NTOT * HID];
__device__ float g_h  [(size_t)NTOT * HID];
__device__ float g_x2 [(size_t)NTOT * OUT_DIM];
__device__ float g_W01T[512 * IN_DIM];          // [W0^T ; Wres^T], tf32
__device__ float g_W1T [OUT_DIM * HID];         // W1^T, tf32
__device__ int   g_cnt [NBUCK];
__device__ int   g_cnt2[NBUCK];
__device__ int   g_off [NBUCK + 1];
__device__ int   g_srow[N_EDGES];
__device__ int   g_scol[N_EDGES];
__device__ float g_sval[N_EDGES];

__device__ __forceinline__ float to_tf32(float x) {
    uint32_t u;
    asm("cvt.rna.tf32.f32 %0, %1;" : "=r"(u) : "f"(x));
    return __uint_as_float(u);
}
__device__ __forceinline__ uint32_t tf32u(float x) {
    uint32_t u;
    asm("cvt.rna.tf32.f32 %0, %1;" : "=r"(u) : "f"(x));
    return u;
}
__device__ __forceinline__ void mma_tf32(float* c, const uint32_t* a, const uint32_t* b) {
    asm volatile(
        "mma.sync.aligned.m16n8k8.row.col.f32.tf32.tf32.f32 "
        "{%0,%1,%2,%3}, {%4,%5,%6,%7}, {%8,%9}, {%0,%1,%2,%3};"
        : "+f"(c[0]), "+f"(c[1]), "+f"(c[2]), "+f"(c[3])
        : "r"(a[0]), "r"(a[1]), "r"(a[2]), "r"(a[3]), "r"(b[0]), "r"(b[1]));
}
__device__ __forceinline__ uint32_t smem_u32(const void* p) {
    uint32_t a;
    asm("{ .reg .u64 t; cvta.to.shared.u64 t, %1; cvt.u32.u64 %0, t; }" : "=r"(a) : "l"(p));
    return a;
}
__device__ __forceinline__ void cp16(uint32_t dst, const void* src, bool pred) {
    int sz = pred ? 16 : 0;
    asm volatile("cp.async.ca.shared.global [%0], [%1], 16, %2;"
                 :: "r"(dst), "l"(src), "r"(sz) : "memory");
}
__device__ __forceinline__ void cp_commit() {
    asm volatile("cp.async.commit_group;" ::: "memory");
}
__device__ __forceinline__ void cp_wait1() {
    asm volatile("cp.async.wait_group 1;" ::: "memory");
}
__device__ __forceinline__ void cp_wait0() {
    asm volatile("cp.async.wait_group 0;" ::: "memory");
}

#define PAD 36
#define TILEF (128 * PAD)   // floats per tile buffer (4608)

// ---------------------------------------------------------------------------
// Weight transpose + tf32 pre-round
// ---------------------------------------------------------------------------
__global__ void transpose_weights(const float* __restrict__ W0,
                                  const float* __restrict__ Wres,
                                  const float* __restrict__ W1) {
    int idx = blockIdx.x * 256 + threadIdx.x;
    if (idx < IN_DIM * HID) {
        int k = idx / HID, n = idx % HID;
        g_W01T[n * IN_DIM + k]         = to_tf32(W0[idx]);
        g_W01T[(n + 256) * IN_DIM + k] = to_tf32(Wres[idx]);
    }
    if (idx < HID * OUT_DIM) {
        int k = idx / OUT_DIM, n = idx % OUT_DIM;
        g_W1T[n * HID + k] = to_tf32(W1[idx]);
    }
}

// ---------------------------------------------------------------------------
// Edge counting-sort by row bucket (row >> 6)
// ---------------------------------------------------------------------------
__global__ __launch_bounds__(256) void edge_hist(const int* __restrict__ rows) {
    int e = blockIdx.x * 256 + threadIdx.x;
    if (e < N_EDGES) atomicAdd(&g_cnt[rows[e] >> BSHIFT], 1);
}

__global__ __launch_bounds__(1024) void bucket_scan() {
    __shared__ int s[2][SCAN_N];
    const int tid = threadIdx.x;
    #pragma unroll
    for (int i = tid; i < SCAN_N; i += 1024)
        s[0][i] = (i > 0 && i - 1 < NBUCK) ? g_cnt[i - 1] : 0;
    __syncthreads();
    int p = 0;
    #pragma unroll
    for (int d = 1; d < SCAN_N; d <<= 1) {
        #pragma unroll
        for (int i = tid; i < SCAN_N; i += 1024)
            s[p ^ 1][i] = s[p][i] + ((i >= d) ? s[p][i - d] : 0);
        p ^= 1;
        __syncthreads();
    }
    #pragma unroll
    for (int i = tid; i < SCAN_N; i += 1024)
        if (i <= NBUCK) g_off[i] = s[p][i];
}

__global__ __launch_bounds__(256) void edge_scatter(
    const int* __restrict__ rows, const int* __restrict__ cols,
    const float* __restrict__ vals) {
    int e = blockIdx.x * 256 + threadIdx.x;
    if (e >= N_EDGES) return;
    int r = rows[e];
    int b = r >> BSHIFT;
    int pos = g_off[b] + atomicAdd(&g_cnt2[b], 1);
    g_srow[pos] = r;
    g_scol[pos] = cols[e];
    g_sval[pos] = vals[e];
}

// ---------------------------------------------------------------------------
// GEMM0 (tf32 mma, cp.async 2-stage): [x | h] = feat @ [W0 | Wres] (+b0)
// grid = (4 nblk, n_mtiles). A staged raw fp32, cvt at fragment read.
// ---------------------------------------------------------------------------
#define G_SMEM (4 * TILEF * 4)   // 73728 B
__global__ __launch_bounds__(256, 2) void gemm0_mma(
    const float* __restrict__ uf, const float* __restrict__ itf,
    const float* __restrict__ b0)
{
    extern __shared__ float smem[];
    float* Asb[2] = { smem, smem + TILEF };
    float* Bsb[2] = { smem + 2 * TILEF, smem + 3 * TILEF };
    const uint32_t sb = smem_u32(smem);

    const int tid = threadIdx.x, lane = tid & 31, wid = tid >> 5;
    const int wm = (wid & 3) * 32, wn = (wid >> 2) * 64;
    const int nblk = blockIdx.x;                  // 0..3
    const int bm = blockIdx.y * 128;
    const float* WT = g_W01T + (size_t)nblk * 128 * IN_DIM;
    const int g = lane >> 2, t = lane & 3;

    // load-thread coordinates
    const int lr = tid >> 3;            // 0..31 base row step 32 over i
    const int lc4 = (tid & 7) * 4;      // col in floats

    float acc[2][8][4];
    #pragma unroll
    for (int i = 0; i < 2; i++)
        #pragma unroll
        for (int j = 0; j < 8; j++)
            #pragma unroll
            for (int q = 0; q < 4; q++) acc[i][j][q] = 0.f;

    const int NC = IN_DIM / 32;  // 4

    // stage loader
    auto issue = [&](int ck, int p) {
        const int k0 = ck * 32;
        uint32_t a_s = sb + (uint32_t)((Asb[p] - smem) * 4);
        uint32_t b_s = sb + (uint32_t)((Bsb[p] - smem) * 4);
        #pragma unroll
        for (int i = 0; i < 4; i++) {
            int r = i * 32 + lr;
            int rg = bm + r;
            const float* src;
            bool ok = rg < NTOT;
            if (rg < N_USERS)      src = uf + (size_t)rg * IN_DIM + k0 + lc4;
            else if (ok)           src = itf + (size_t)(rg - N_USERS) * IN_DIM + k0 + lc4;
            else                   src = uf;  // dummy, zfill
            cp16(a_s + (uint32_t)(r * PAD + lc4) * 4, src, ok);
        }
        #pragma unroll
        for (int i = 0; i < 4; i++) {
            int r = i * 32 + lr;
            cp16(b_s + (uint32_t)(r * PAD + lc4) * 4,
                 WT + (size_t)r * IN_DIM + k0 + lc4, true);
        }
        cp_commit();
    };

    issue(0, 0);
    for (int ck = 0; ck < NC; ck++) {
        const int p = ck & 1;
        if (ck + 1 < NC) { issue(ck + 1, p ^ 1); cp_wait1(); }
        else             { cp_wait0(); }
        __syncthreads();
        float* As = Asb[p];
        float* Bs = Bsb[p];
        #pragma unroll
        for (int kk = 0; kk < 4; kk++) {
            const int kb = kk * 8;
            uint32_t a[2][4];
            #pragma unroll
            for (int fm = 0; fm < 2; fm++) {
                int r0 = wm + fm * 16 + g;
                a[fm][0] = tf32u(As[r0 * PAD + kb + t]);
                a[fm][1] = tf32u(As[(r0 + 8) * PAD + kb + t]);
                a[fm][2] = tf32u(As[r0 * PAD + kb + t + 4]);
                a[fm][3] = tf32u(As[(r0 + 8) * PAD + kb + t + 4]);
            }
            #pragma unroll
            for (int nf = 0; nf < 8; nf++) {
                uint32_t b[2];
                int rn = wn + nf * 8 + g;
                b[0] = __float_as_uint(Bs[rn * PAD + kb + t]);
                b[1] = __float_as_uint(Bs[rn * PAD + kb + t + 4]);
                mma_tf32(acc[0][nf], a[0], b);
                mma_tf32(acc[1][nf], a[1], b);
            }
        }
        __syncthreads();
    }

    float* dst = (nblk < 2) ? g_x : g_h;
    const bool addb = (nblk < 2);
    const int cbase = (nblk & 1) * 128 + wn;
    #pragma unroll
    for (int fm = 0; fm < 2; fm++) {
        int row = bm + wm + fm * 16 + g;
        #pragma unroll
        for (int nf = 0; nf < 8; nf++) {
            int col = cbase + nf * 8 + 2 * t;
            float bv0 = 0.f, bv1 = 0.f;
            if (addb) { bv0 = __ldg(b0 + col); bv1 = __ldg(b0 + col + 1); }
            if (row < NTOT)
                *(float2*)(dst + (size_t)row * 256 + col) =
                    make_float2(acc[fm][nf][0] + bv0, acc[fm][nf][1] + bv1);
            if (row + 8 < NTOT)
                *(float2*)(dst + (size_t)(row + 8) * 256 + col) =
                    make_float2(acc[fm][nf][2] + bv0, acc[fm][nf][3] + bv1);
        }
    }
}

// ---------------------------------------------------------------------------
// GEMM1 (tf32 mma, cp.async 2-stage): x2 = relu(h) @ W1 + b1
// grid = (2 nblk, n_mtiles). relu+cvt at fragment read.
// ---------------------------------------------------------------------------
__global__ __launch_bounds__(256, 2) void gemm1_mma(const float* __restrict__ b1)
{
    extern __shared__ float smem[];
    float* Asb[2] = { smem, smem + TILEF };
    float* Bsb[2] = { smem + 2 * TILEF, smem + 3 * TILEF };
    const uint32_t sb = smem_u32(smem);

    const int tid = threadIdx.x, lane = tid & 31, wid = tid >> 5;
    const int wm = (wid & 3) * 32, wn = (wid >> 2) * 64;
    const int nblk = blockIdx.x;                 // 0..1
    const int bm = blockIdx.y * 128;
    const int g = lane >> 2, t = lane & 3;
    const int lr = tid >> 3;
    const int lc4 = (tid & 7) * 4;

    float acc[2][8][4];
    #pragma unroll
    for (int i = 0; i < 2; i++)
        #pragma unroll
        for (int j = 0; j < 8; j++)
            #pragma unroll
            for (int q = 0; q < 4; q++) acc[i][j][q] = 0.f;

    const int NC = HID / 32;  // 8

    auto issue = [&](int ck, int p) {
        const int k0 = ck * 32;
        uint32_t a_s = sb + (uint32_t)((Asb[p] - smem) * 4);
        uint32_t b_s = sb + (uint32_t)((Bsb[p] - smem) * 4);
        #pragma unroll
        for (int i = 0; i < 4; i++) {
            int r = i * 32 + lr;
            int rg = bm + r;
            bool ok = rg < NTOT;
            const float* src = ok ? g_h + (size_t)rg * HID + k0 + lc4 : g_h;
            cp16(a_s + (uint32_t)(r * PAD + lc4) * 4, src, ok);
        }
        #pragma unroll
        for (int i = 0; i < 4; i++) {
            int r = i * 32 + lr;
            cp16(b_s + (uint32_t)(r * PAD + lc4) * 4,
                 g_W1T + (size_t)(nblk * 128 + r) * HID + k0 + lc4, true);
        }
        cp_commit();
    };

    issue(0, 0);
    for (int ck = 0; ck < NC; ck++) {
        const int p = ck & 1;
        if (ck + 1 < NC) { issue(ck + 1, p ^ 1); cp_wait1(); }
        else             { cp_wait0(); }
        __syncthreads();
        float* As = Asb[p];
        float* Bs = Bsb[p];
        #pragma unroll
        for (int kk = 0; kk < 4; kk++) {
            const int kb = kk * 8;
            uint32_t a[2][4];
            #pragma unroll
            for (int fm = 0; fm < 2; fm++) {
                int r0 = wm + fm * 16 + g;
                a[fm][0] = tf32u(fmaxf(As[r0 * PAD + kb + t], 0.f));
                a[fm][1] = tf32u(fmaxf(As[(r0 + 8) * PAD + kb + t], 0.f));
                a[fm][2] = tf32u(fmaxf(As[r0 * PAD + kb + t + 4], 0.f));
                a[fm][3] = tf32u(fmaxf(As[(r0 + 8) * PAD + kb + t + 4], 0.f));
            }
            #pragma unroll
            for (int nf = 0; nf < 8; nf++) {
                uint32_t b[2];
                int rn = wn + nf * 8 + g;
                b[0] = __float_as_uint(Bs[rn * PAD + kb + t]);
                b[1] = __float_as_uint(Bs[rn * PAD + kb + t + 4]);
                mma_tf32(acc[0][nf], a[0], b);
                mma_tf32(acc[1][nf], a[1], b);
            }
        }
        __syncthreads();
    }

    const int cbase = nblk * 128 + wn;
    #pragma unroll
    for (int fm = 0; fm < 2; fm++) {
        int row = bm + wm + fm * 16 + g;
        #pragma unroll
        for (int nf = 0; nf < 8; nf++) {
            int col = cbase + nf * 8 + 2 * t;
            float bv0 = __ldg(b1 + col), bv1 = __ldg(b1 + col + 1);
            if (row < NTOT)
                *(float2*)(g_x2 + (size_t)row * 256 + col) =
                    make_float2(acc[fm][nf][0] + bv0, acc[fm][nf][1] + bv1);
            if (row + 8 < NTOT)
                *(float2*)(g_x2 + (size_t)(row + 8) * 256 + col) =
                    make_float2(acc[fm][nf][2] + bv0, acc[fm][nf][3] + bv1);
        }
    }
}

// ---------------------------------------------------------------------------
// Bucket SpMM: block b owns rows [b*64, b*64+64). Thread tid owns column tid.
// No atomics, no syncs in the accumulate loop (columns are thread-private).
// ADD variant: Y += acc (layer-0, Y holds residual). SET variant: Y = acc.
// ---------------------------------------------------------------------------
#define SPMM_SMEM (BROWS * 256 * 4)   // 65536
template <bool ADD>
__global__ __launch_bounds__(256) void spmm_bucket(
    const float* __restrict__ X, float* __restrict__ Y)
{
    extern __shared__ float acc[];
    const int b = blockIdx.x;
    const int tid = threadIdx.x;
    const int e0 = g_off[b], e1 = g_off[b + 1];

    #pragma unroll
    for (int r = 0; r < BROWS; r++) acc[r * 256 + tid] = 0.f;

    int e = e0;
    for (; e + 4 <= e1; e += 4) {
        int r0 = g_srow[e    ] & (BROWS - 1), c0 = g_scol[e    ];
        int r1 = g_srow[e + 1] & (BROWS - 1), c1 = g_scol[e + 1];
        int r2 = g_srow[e + 2] & (BROWS - 1), c2 = g_scol[e + 2];
        int r3 = g_srow[e + 3] & (BROWS - 1), c3 = g_scol[e + 3];
        float v0 = g_sval[e], v1 = g_sval[e + 1], v2 = g_sval[e + 2], v3 = g_sval[e + 3];
        float x0 = __ldg(X + (size_t)c0 * 256 + tid);
        float x1 = __ldg(X + (size_t)c1 * 256 + tid);
        float x2 = __ldg(X + (size_t)c2 * 256 + tid);
        float x3 = __ldg(X + (size_t)c3 * 256 + tid);
        acc[r0 * 256 + tid] += v0 * x0;
        acc[r1 * 256 + tid] += v1 * x1;
        acc[r2 * 256 + tid] += v2 * x2;
        acc[r3 * 256 + tid] += v3 * x3;
    }
    for (; e < e1; e++) {
        int r = g_srow[e] & (BROWS - 1);
        int c = g_scol[e];
        float v = g_sval[e];
        acc[r * 256 + tid] += v * __ldg(X + (size_t)c * 256 + tid);
    }

    const int row0 = b << BSHIFT;
    #pragma unroll
    for (int r = 0; r < BROWS; r++) {
        int row = row0 + r;
        if (row < NTOT) {
            if (ADD) Y[(size_t)row * 256 + tid] += acc[r * 256 + tid];
            else     Y[(size_t)row * 256 + tid]  = acc[r * 256 + tid];
        }
    }
}

// ---------------------------------------------------------------------------
extern "C" void kernel_launch(void* const* d_in, const int* in_sizes, int n_in,
                              void* d_out, int out_size)
{
    const float* user_feat = (const float*)d_in[0];
    const float* item_feat = (const float*)d_in[1];
    const int*   edge_rows = (const int*)  d_in[2];
    const int*   edge_cols = (const int*)  d_in[3];
    const float* edge_vals = (const float*)d_in[4];
    const float* W0        = (const float*)d_in[5];
    const float* b0        = (const float*)d_in[6];
    const float* Wres0     = (const float*)d_in[7];
    const float* W1        = (const float*)d_in[8];
    const float* b1        = (const float*)d_in[9];
    float* out = (float*)d_out;

    float* gx;  cudaGetSymbolAddress((void**)&gx,  g_x);
    float* gh;  cudaGetSymbolAddress((void**)&gh,  g_h);
    float* gx2; cudaGetSymbolAddress((void**)&gx2, g_x2);
    int* cnt;   cudaGetSymbolAddress((void**)&cnt,  g_cnt);
    int* cnt2;  cudaGetSymbolAddress((void**)&cnt2, g_cnt2);

    cudaFuncSetAttribute(gemm0_mma, cudaFuncAttributeMaxDynamicSharedMemorySize, G_SMEM);
    cudaFuncSetAttribute(gemm1_mma, cudaFuncAttributeMaxDynamicSharedMemorySize, G_SMEM);
    cudaFuncSetAttribute(spmm_bucket<true>,  cudaFuncAttributeMaxDynamicSharedMemorySize, SPMM_SMEM);
    cudaFuncSetAttribute(spmm_bucket<false>, cudaFuncAttributeMaxDynamicSharedMemorySize, SPMM_SMEM);

    const int n_mtiles = (NTOT + 127) / 128;
    const int eb = (N_EDGES + 255) / 256;

    // --- edge sort chain (reused by both SpMMs) ---
    cudaMemsetAsync(cnt,  0, NBUCK * sizeof(int));
    cudaMemsetAsync(cnt2, 0, NBUCK * sizeof(int));
    edge_hist<<<eb, 256>>>(edge_rows);
    bucket_scan<<<1, 1024>>>();
    edge_scatter<<<eb, 256>>>(edge_rows, edge_cols, edge_vals);

    // weights -> K-major tf32 transposed copies
    transpose_weights<<<(HID * OUT_DIM + 255) / 256, 256>>>(W0, Wres0, W1);

    // Layer 0: x = feat@W0+b0 ; h = feat@Wres0
    gemm0_mma<<<dim3(4, n_mtiles), 256, G_SMEM>>>(user_feat, item_feat, b0);

    // h += A @ x   (bucket smem, no atomics)
    spmm_bucket<true><<<NBUCK, 256, SPMM_SMEM>>>(gx, gh);

    // Layer 1: x2 = relu(h)@W1 + b1
    gemm1_mma<<<dim3(2, n_mtiles), 256, G_SMEM>>>(b1);

    // out = A @ x2   (direct write, covers every row -> no memset needed)
    spmm_bucket<false><<<NBUCK, 256, SPMM_SMEM>>>(gx2, out);
}

// round 6
// speedup vs baseline: 1.7296x; 1.7296x over previous
#include <cuda_runtime.h>
#include <cstdint>

#define N_USERS  40000
#define NTOT     100000
#define IN_DIM   128
#define HID      256
#define OUT_DIM  256
#define N_EDGES  600000

#define BSHIFT   6
#define NBUCK    ((NTOT + 63) >> BSHIFT)   // 1563
#define SCAN_N   2048

// Scratch (allocation-free rule: device globals)
__device__ float g_x  [(size_t)NTOT * HID];
__device__ float g_h  [(size_t)NTOT * HID];
__device__ float g_x2 [(size_t)NTOT * OUT_DIM];
__device__ float g_W01T[512 * IN_DIM];          // [W0^T ; Wres^T], tf32
__device__ float g_W1T [OUT_DIM * HID];         // W1^T, tf32
__device__ int   g_cnt [NBUCK];
__device__ int   g_cnt2[NBUCK];
__device__ int   g_off [NBUCK + 1];
__device__ int   g_srow[N_EDGES];
__device__ int   g_scol[N_EDGES];
__device__ float g_sval[N_EDGES];

__device__ __forceinline__ float to_tf32(float x) {
    uint32_t u;
    asm("cvt.rna.tf32.f32 %0, %1;" : "=r"(u) : "f"(x));
    return __uint_as_float(u);
}
__device__ __forceinline__ uint32_t tf32u(float x) {
    uint32_t u;
    asm("cvt.rna.tf32.f32 %0, %1;" : "=r"(u) : "f"(x));
    return u;
}
__device__ __forceinline__ void mma_tf32(float* c, const uint32_t* a, const uint32_t* b) {
    asm volatile(
        "mma.sync.aligned.m16n8k8.row.col.f32.tf32.tf32.f32 "
        "{%0,%1,%2,%3}, {%4,%5,%6,%7}, {%8,%9}, {%0,%1,%2,%3};"
        : "+f"(c[0]), "+f"(c[1]), "+f"(c[2]), "+f"(c[3])
        : "r"(a[0]), "r"(a[1]), "r"(a[2]), "r"(a[3]), "r"(b[0]), "r"(b[1]));
}
__device__ __forceinline__ uint32_t smem_u32(const void* p) {
    uint32_t a;
    asm("{ .reg .u64 t; cvta.to.shared.u64 t, %1; cvt.u32.u64 %0, t; }" : "=r"(a) : "l"(p));
    return a;
}
__device__ __forceinline__ void cp16(uint32_t dst, const void* src, bool pred) {
    int sz = pred ? 16 : 0;
    asm volatile("cp.async.ca.shared.global [%0], [%1], 16, %2;"
                 :: "r"(dst), "l"(src), "r"(sz) : "memory");
}
__device__ __forceinline__ void cp_commit() {
    asm volatile("cp.async.commit_group;" ::: "memory");
}
__device__ __forceinline__ void cp_wait1() {
    asm volatile("cp.async.wait_group 1;" ::: "memory");
}
__device__ __forceinline__ void cp_wait0() {
    asm volatile("cp.async.wait_group 0;" ::: "memory");
}

#define PAD 36
#define TILEF (128 * PAD)   // floats per tile buffer

// ---------------------------------------------------------------------------
// Weight transpose + tf32 pre-round
// ---------------------------------------------------------------------------
__global__ void transpose_weights(const float* __restrict__ W0,
                                  const float* __restrict__ Wres,
                                  const float* __restrict__ W1) {
    int idx = blockIdx.x * 256 + threadIdx.x;
    if (idx < IN_DIM * HID) {
        int k = idx / HID, n = idx % HID;
        g_W01T[n * IN_DIM + k]         = to_tf32(W0[idx]);
        g_W01T[(n + 256) * IN_DIM + k] = to_tf32(Wres[idx]);
    }
    if (idx < HID * OUT_DIM) {
        int k = idx / OUT_DIM, n = idx % OUT_DIM;
        g_W1T[n * HID + k] = to_tf32(W1[idx]);
    }
}

// ---------------------------------------------------------------------------
// Edge counting-sort by row bucket (row >> 6)
// ---------------------------------------------------------------------------
__global__ __launch_bounds__(256) void edge_hist(const int* __restrict__ rows) {
    int e = blockIdx.x * 256 + threadIdx.x;
    if (e < N_EDGES) atomicAdd(&g_cnt[rows[e] >> BSHIFT], 1);
}

__global__ __launch_bounds__(1024) void bucket_scan() {
    __shared__ int s[2][SCAN_N];
    const int tid = threadIdx.x;
    #pragma unroll
    for (int i = tid; i < SCAN_N; i += 1024)
        s[0][i] = (i > 0 && i - 1 < NBUCK) ? g_cnt[i - 1] : 0;
    __syncthreads();
    int p = 0;
    #pragma unroll
    for (int d = 1; d < SCAN_N; d <<= 1) {
        #pragma unroll
        for (int i = tid; i < SCAN_N; i += 1024)
            s[p ^ 1][i] = s[p][i] + ((i >= d) ? s[p][i - d] : 0);
        p ^= 1;
        __syncthreads();
    }
    #pragma unroll
    for (int i = tid; i < SCAN_N; i += 1024)
        if (i <= NBUCK) g_off[i] = s[p][i];
}

__global__ __launch_bounds__(256) void edge_scatter(
    const int* __restrict__ rows, const int* __restrict__ cols,
    const float* __restrict__ vals) {
    int e = blockIdx.x * 256 + threadIdx.x;
    if (e >= N_EDGES) return;
    int r = rows[e];
    int b = r >> BSHIFT;
    int pos = g_off[b] + atomicAdd(&g_cnt2[b], 1);
    g_srow[pos] = r;
    g_scol[pos] = cols[e];
    g_sval[pos] = vals[e];
}

// ---------------------------------------------------------------------------
// GEMM0 (tf32 mma, cp.async 2-stage): [x | h] = feat @ [W0 | Wres] (+b0)
// ---------------------------------------------------------------------------
#define G_SMEM (4 * TILEF * 4)   // 73728 B
__global__ __launch_bounds__(256, 2) void gemm0_mma(
    const float* __restrict__ uf, const float* __restrict__ itf,
    const float* __restrict__ b0)
{
    extern __shared__ float smem[];
    float* Asb[2] = { smem, smem + TILEF };
    float* Bsb[2] = { smem + 2 * TILEF, smem + 3 * TILEF };
    const uint32_t sb = smem_u32(smem);

    const int tid = threadIdx.x, lane = tid & 31, wid = tid >> 5;
    const int wm = (wid & 3) * 32, wn = (wid >> 2) * 64;
    const int nblk = blockIdx.x;                  // 0..3
    const int bm = blockIdx.y * 128;
    const float* WT = g_W01T + (size_t)nblk * 128 * IN_DIM;
    const int g = lane >> 2, t = lane & 3;
    const int lr = tid >> 3;
    const int lc4 = (tid & 7) * 4;

    float acc[2][8][4];
    #pragma unroll
    for (int i = 0; i < 2; i++)
        #pragma unroll
        for (int j = 0; j < 8; j++)
            #pragma unroll
            for (int q = 0; q < 4; q++) acc[i][j][q] = 0.f;

    const int NC = IN_DIM / 32;  // 4

    auto issue = [&](int ck, int p) {
        const int k0 = ck * 32;
        uint32_t a_s = sb + (uint32_t)((Asb[p] - smem) * 4);
        uint32_t b_s = sb + (uint32_t)((Bsb[p] - smem) * 4);
        #pragma unroll
        for (int i = 0; i < 4; i++) {
            int r = i * 32 + lr;
            int rg = bm + r;
            const float* src;
            bool ok = rg < NTOT;
            if (rg < N_USERS)      src = uf + (size_t)rg * IN_DIM + k0 + lc4;
            else if (ok)           src = itf + (size_t)(rg - N_USERS) * IN_DIM + k0 + lc4;
            else                   src = uf;
            cp16(a_s + (uint32_t)(r * PAD + lc4) * 4, src, ok);
        }
        #pragma unroll
        for (int i = 0; i < 4; i++) {
            int r = i * 32 + lr;
            cp16(b_s + (uint32_t)(r * PAD + lc4) * 4,
                 WT + (size_t)r * IN_DIM + k0 + lc4, true);
        }
        cp_commit();
    };

    issue(0, 0);
    for (int ck = 0; ck < NC; ck++) {
        const int p = ck & 1;
        if (ck + 1 < NC) { issue(ck + 1, p ^ 1); cp_wait1(); }
        else             { cp_wait0(); }
        __syncthreads();
        float* As = Asb[p];
        float* Bs = Bsb[p];
        #pragma unroll
        for (int kk = 0; kk < 4; kk++) {
            const int kb = kk * 8;
            uint32_t a[2][4];
            #pragma unroll
            for (int fm = 0; fm < 2; fm++) {
                int r0 = wm + fm * 16 + g;
                a[fm][0] = tf32u(As[r0 * PAD + kb + t]);
                a[fm][1] = tf32u(As[(r0 + 8) * PAD + kb + t]);
                a[fm][2] = tf32u(As[r0 * PAD + kb + t + 4]);
                a[fm][3] = tf32u(As[(r0 + 8) * PAD + kb + t + 4]);
            }
            #pragma unroll
            for (int nf = 0; nf < 8; nf++) {
                uint32_t b[2];
                int rn = wn + nf * 8 + g;
                b[0] = __float_as_uint(Bs[rn * PAD + kb + t]);
                b[1] = __float_as_uint(Bs[rn * PAD + kb + t + 4]);
                mma_tf32(acc[0][nf], a[0], b);
                mma_tf32(acc[1][nf], a[1], b);
            }
        }
        __syncthreads();
    }

    float* dst = (nblk < 2) ? g_x : g_h;
    const bool addb = (nblk < 2);
    const int cbase = (nblk & 1) * 128 + wn;
    #pragma unroll
    for (int fm = 0; fm < 2; fm++) {
        int row = bm + wm + fm * 16 + g;
        #pragma unroll
        for (int nf = 0; nf < 8; nf++) {
            int col = cbase + nf * 8 + 2 * t;
            float bv0 = 0.f, bv1 = 0.f;
            if (addb) { bv0 = __ldg(b0 + col); bv1 = __ldg(b0 + col + 1); }
            if (row < NTOT)
                *(float2*)(dst + (size_t)row * 256 + col) =
                    make_float2(acc[fm][nf][0] + bv0, acc[fm][nf][1] + bv1);
            if (row + 8 < NTOT)
                *(float2*)(dst + (size_t)(row + 8) * 256 + col) =
                    make_float2(acc[fm][nf][2] + bv0, acc[fm][nf][3] + bv1);
        }
    }
}

// ---------------------------------------------------------------------------
// GEMM1 (tf32 mma, cp.async 2-stage): x2 = relu(h) @ W1 + b1
// ---------------------------------------------------------------------------
__global__ __launch_bounds__(256, 2) void gemm1_mma(const float* __restrict__ b1)
{
    extern __shared__ float smem[];
    float* Asb[2] = { smem, smem + TILEF };
    float* Bsb[2] = { smem + 2 * TILEF, smem + 3 * TILEF };
    const uint32_t sb = smem_u32(smem);

    const int tid = threadIdx.x, lane = tid & 31, wid = tid >> 5;
    const int wm = (wid & 3) * 32, wn = (wid >> 2) * 64;
    const int nblk = blockIdx.x;                 // 0..1
    const int bm = blockIdx.y * 128;
    const int g = lane >> 2, t = lane & 3;
    const int lr = tid >> 3;
    const int lc4 = (tid & 7) * 4;

    float acc[2][8][4];
    #pragma unroll
    for (int i = 0; i < 2; i++)
        #pragma unroll
        for (int j = 0; j < 8; j++)
            #pragma unroll
            for (int q = 0; q < 4; q++) acc[i][j][q] = 0.f;

    const int NC = HID / 32;  // 8

    auto issue = [&](int ck, int p) {
        const int k0 = ck * 32;
        uint32_t a_s = sb + (uint32_t)((Asb[p] - smem) * 4);
        uint32_t b_s = sb + (uint32_t)((Bsb[p] - smem) * 4);
        #pragma unroll
        for (int i = 0; i < 4; i++) {
            int r = i * 32 + lr;
            int rg = bm + r;
            bool ok = rg < NTOT;
            const float* src = ok ? g_h + (size_t)rg * HID + k0 + lc4 : g_h;
            cp16(a_s + (uint32_t)(r * PAD + lc4) * 4, src, ok);
        }
        #pragma unroll
        for (int i = 0; i < 4; i++) {
            int r = i * 32 + lr;
            cp16(b_s + (uint32_t)(r * PAD + lc4) * 4,
                 g_W1T + (size_t)(nblk * 128 + r) * HID + k0 + lc4, true);
        }
        cp_commit();
    };

    issue(0, 0);
    for (int ck = 0; ck < NC; ck++) {
        const int p = ck & 1;
        if (ck + 1 < NC) { issue(ck + 1, p ^ 1); cp_wait1(); }
        else             { cp_wait0(); }
        __syncthreads();
        float* As = Asb[p];
        float* Bs = Bsb[p];
        #pragma unroll
        for (int kk = 0; kk < 4; kk++) {
            const int kb = kk * 8;
            uint32_t a[2][4];
            #pragma unroll
            for (int fm = 0; fm < 2; fm++) {
                int r0 = wm + fm * 16 + g;
                a[fm][0] = tf32u(fmaxf(As[r0 * PAD + kb + t], 0.f));
                a[fm][1] = tf32u(fmaxf(As[(r0 + 8) * PAD + kb + t], 0.f));
                a[fm][2] = tf32u(fmaxf(As[r0 * PAD + kb + t + 4], 0.f));
                a[fm][3] = tf32u(fmaxf(As[(r0 + 8) * PAD + kb + t + 4], 0.f));
            }
            #pragma unroll
            for (int nf = 0; nf < 8; nf++) {
                uint32_t b[2];
                int rn = wn + nf * 8 + g;
                b[0] = __float_as_uint(Bs[rn * PAD + kb + t]);
                b[1] = __float_as_uint(Bs[rn * PAD + kb + t + 4]);
                mma_tf32(acc[0][nf], a[0], b);
                mma_tf32(acc[1][nf], a[1], b);
            }
        }
        __syncthreads();
    }

    const int cbase = nblk * 128 + wn;
    #pragma unroll
    for (int fm = 0; fm < 2; fm++) {
        int row = bm + wm + fm * 16 + g;
        #pragma unroll
        for (int nf = 0; nf < 8; nf++) {
            int col = cbase + nf * 8 + 2 * t;
            float bv0 = __ldg(b1 + col), bv1 = __ldg(b1 + col + 1);
            if (row < NTOT)
                *(float2*)(g_x2 + (size_t)row * 256 + col) =
                    make_float2(acc[fm][nf][0] + bv0, acc[fm][nf][1] + bv1);
            if (row + 8 < NTOT)
                *(float2*)(g_x2 + (size_t)(row + 8) * 256 + col) =
                    make_float2(acc[fm][nf][2] + bv0, acc[fm][nf][3] + bv1);
        }
    }
}

// ---------------------------------------------------------------------------
// SpMM over row-sorted edges: Y[row] += val * X[col], warp per edge.
// (round-4 known-good version)
// ---------------------------------------------------------------------------
__global__ __launch_bounds__(256) void spmm_sorted(
    const float* __restrict__ X, float* __restrict__ Y)
{
    int e = blockIdx.x * 8 + (threadIdx.x >> 5);
    if (e >= N_EDGES) return;
    const int lane = threadIdx.x & 31;
    const int r = g_srow[e];
    const int c = g_scol[e];
    const float v = g_sval[e];
    const float* xp = X + (size_t)c * 256;
    float* yp = Y + (size_t)r * 256;
    #pragma unroll
    for (int j = 0; j < 8; j++)
        atomicAdd(yp + j * 32 + lane, v * __ldg(xp + j * 32 + lane));
}

// ---------------------------------------------------------------------------
extern "C" void kernel_launch(void* const* d_in, const int* in_sizes, int n_in,
                              void* d_out, int out_size)
{
    const float* user_feat = (const float*)d_in[0];
    const float* item_feat = (const float*)d_in[1];
    const int*   edge_rows = (const int*)  d_in[2];
    const int*   edge_cols = (const int*)  d_in[3];
    const float* edge_vals = (const float*)d_in[4];
    const float* W0        = (const float*)d_in[5];
    const float* b0        = (const float*)d_in[6];
    const float* Wres0     = (const float*)d_in[7];
    const float* W1        = (const float*)d_in[8];
    const float* b1        = (const float*)d_in[9];
    float* out = (float*)d_out;

    float* gx;  cudaGetSymbolAddress((void**)&gx,  g_x);
    float* gh;  cudaGetSymbolAddress((void**)&gh,  g_h);
    float* gx2; cudaGetSymbolAddress((void**)&gx2, g_x2);
    int* cnt;   cudaGetSymbolAddress((void**)&cnt,  g_cnt);
    int* cnt2;  cudaGetSymbolAddress((void**)&cnt2, g_cnt2);

    cudaFuncSetAttribute(gemm0_mma, cudaFuncAttributeMaxDynamicSharedMemorySize, G_SMEM);
    cudaFuncSetAttribute(gemm1_mma, cudaFuncAttributeMaxDynamicSharedMemorySize, G_SMEM);

    const int n_mtiles = (NTOT + 127) / 128;
    const int eb = (N_EDGES + 255) / 256;

    // --- edge sort chain (reused by both SpMMs) ---
    cudaMemsetAsync(cnt,  0, NBUCK * sizeof(int));
    cudaMemsetAsync(cnt2, 0, NBUCK * sizeof(int));
    edge_hist<<<eb, 256>>>(edge_rows);
    bucket_scan<<<1, 1024>>>();
    edge_scatter<<<eb, 256>>>(edge_rows, edge_cols, edge_vals);

    // weights -> K-major tf32 transposed copies
    transpose_weights<<<(HID * OUT_DIM + 255) / 256, 256>>>(W0, Wres0, W1);

    // Layer 0: x = feat@W0+b0 ; h = feat@Wres0
    gemm0_mma<<<dim3(4, n_mtiles), 256, G_SMEM>>>(user_feat, item_feat, b0);

    cudaMemsetAsync(d_out, 0, (size_t)NTOT * OUT_DIM * sizeof(float));

    // h += A @ x
    spmm_sorted<<<(N_EDGES + 7) / 8, 256>>>(gx, gh);

    // Layer 1: x2 = relu(h)@W1 + b1
    gemm1_mma<<<dim3(2, n_mtiles), 256, G_SMEM>>>(b1);

    // out = A @ x2
    spmm_sorted<<<(N_EDGES + 7) / 8, 256>>>(gx2, out);
}

// round 7
// speedup vs baseline: 1.8155x; 1.0497x over previous
#include <cuda_runtime.h>
#include <cstdint>

#define N_USERS  40000
#define NTOT     100000
#define IN_DIM   128
#define HID      256
#define OUT_DIM  256
#define N_EDGES  600000

// Scratch (allocation-free rule: device globals)
__device__ float g_x  [(size_t)NTOT * HID];
__device__ float g_h  [(size_t)NTOT * HID];
__device__ float g_x2 [(size_t)NTOT * OUT_DIM];
__device__ float g_W01T[512 * IN_DIM];          // [W0^T ; Wres^T], tf32
__device__ float g_W1T [OUT_DIM * HID];         // W1^T, tf32
__device__ int   g_rcnt [NTOT];
__device__ int   g_rcnt2[NTOT];
__device__ int   g_rptr [NTOT + 1];
__device__ int   g_scol[N_EDGES];
__device__ float g_sval[N_EDGES];

__device__ __forceinline__ float to_tf32(float x) {
    uint32_t u;
    asm("cvt.rna.tf32.f32 %0, %1;" : "=r"(u) : "f"(x));
    return __uint_as_float(u);
}
__device__ __forceinline__ uint32_t tf32u(float x) {
    uint32_t u;
    asm("cvt.rna.tf32.f32 %0, %1;" : "=r"(u) : "f"(x));
    return u;
}
__device__ __forceinline__ void mma_tf32(float* c, const uint32_t* a, const uint32_t* b) {
    asm volatile(
        "mma.sync.aligned.m16n8k8.row.col.f32.tf32.tf32.f32 "
        "{%0,%1,%2,%3}, {%4,%5,%6,%7}, {%8,%9}, {%0,%1,%2,%3};"
        : "+f"(c[0]), "+f"(c[1]), "+f"(c[2]), "+f"(c[3])
        : "r"(a[0]), "r"(a[1]), "r"(a[2]), "r"(a[3]), "r"(b[0]), "r"(b[1]));
}
__device__ __forceinline__ uint32_t smem_u32(const void* p) {
    uint32_t a;
    asm("{ .reg .u64 t; cvta.to.shared.u64 t, %1; cvt.u32.u64 %0, t; }" : "=r"(a) : "l"(p));
    return a;
}
__device__ __forceinline__ void cp16(uint32_t dst, const void* src, bool pred) {
    int sz = pred ? 16 : 0;
    asm volatile("cp.async.ca.shared.global [%0], [%1], 16, %2;"
                 :: "r"(dst), "l"(src), "r"(sz) : "memory");
}
__device__ __forceinline__ void cp_commit() {
    asm volatile("cp.async.commit_group;" ::: "memory");
}
__device__ __forceinline__ void cp_wait1() {
    asm volatile("cp.async.wait_group 1;" ::: "memory");
}
__device__ __forceinline__ void cp_wait0() {
    asm volatile("cp.async.wait_group 0;" ::: "memory");
}

#define PAD 36
#define TILEF (128 * PAD)

// ---------------------------------------------------------------------------
// Weight transpose + tf32 pre-round
// ---------------------------------------------------------------------------
__global__ void transpose_weights(const float* __restrict__ W0,
                                  const float* __restrict__ Wres,
                                  const float* __restrict__ W1) {
    int idx = blockIdx.x * 256 + threadIdx.x;
    if (idx < IN_DIM * HID) {
        int k = idx / HID, n = idx % HID;
        g_W01T[n * IN_DIM + k]         = to_tf32(W0[idx]);
        g_W01T[(n + 256) * IN_DIM + k] = to_tf32(Wres[idx]);
    }
    if (idx < HID * OUT_DIM) {
        int k = idx / OUT_DIM, n = idx % OUT_DIM;
        g_W1T[n * HID + k] = to_tf32(W1[idx]);
    }
}

// ---------------------------------------------------------------------------
// CSR build: per-row histogram -> 1-block chunked exclusive scan -> scatter
// ---------------------------------------------------------------------------
__global__ __launch_bounds__(256) void row_hist(const int* __restrict__ rows) {
    int e = blockIdx.x * 256 + threadIdx.x;
    if (e < N_EDGES) atomicAdd(&g_rcnt[rows[e]], 1);
}

#define CHUNK 98   // 1024 * 98 = 100352 >= NTOT
__global__ __launch_bounds__(1024) void row_scan() {
    __shared__ int ssum[1024];
    const int tid = threadIdx.x;
    const int base = tid * CHUNK;
    int s = 0;
    #pragma unroll 7
    for (int i = 0; i < CHUNK; i++) {
        int idx = base + i;
        if (idx < NTOT) s += g_rcnt[idx];
    }
    ssum[tid] = s;
    __syncthreads();
    for (int d = 1; d < 1024; d <<= 1) {
        int o = (tid >= d) ? ssum[tid - d] : 0;
        __syncthreads();
        ssum[tid] += o;
        __syncthreads();
    }
    int run = ssum[tid] - s;   // exclusive chunk base
    #pragma unroll 7
    for (int i = 0; i < CHUNK; i++) {
        int idx = base + i;
        if (idx < NTOT) {
            g_rptr[idx] = run;
            run += g_rcnt[idx];
        }
    }
    if (tid == 1023) g_rptr[NTOT] = ssum[1023];
}

__global__ __launch_bounds__(256) void edge_scatter(
    const int* __restrict__ rows, const int* __restrict__ cols,
    const float* __restrict__ vals) {
    int e = blockIdx.x * 256 + threadIdx.x;
    if (e >= N_EDGES) return;
    int r = rows[e];
    int pos = g_rptr[r] + atomicAdd(&g_rcnt2[r], 1);
    g_scol[pos] = cols[e];
    g_sval[pos] = vals[e];
}

// ---------------------------------------------------------------------------
// GEMM0 (tf32 mma, cp.async 2-stage): [x | h] = feat @ [W0 | Wres] (+b0)
// ---------------------------------------------------------------------------
#define G_SMEM (4 * TILEF * 4)   // 73728 B
__global__ __launch_bounds__(256, 2) void gemm0_mma(
    const float* __restrict__ uf, const float* __restrict__ itf,
    const float* __restrict__ b0)
{
    extern __shared__ float smem[];
    float* Asb[2] = { smem, smem + TILEF };
    float* Bsb[2] = { smem + 2 * TILEF, smem + 3 * TILEF };
    const uint32_t sb = smem_u32(smem);

    const int tid = threadIdx.x, lane = tid & 31, wid = tid >> 5;
    const int wm = (wid & 3) * 32, wn = (wid >> 2) * 64;
    const int nblk = blockIdx.x;                  // 0..3
    const int bm = blockIdx.y * 128;
    const float* WT = g_W01T + (size_t)nblk * 128 * IN_DIM;
    const int g = lane >> 2, t = lane & 3;
    const int lr = tid >> 3;
    const int lc4 = (tid & 7) * 4;

    float acc[2][8][4];
    #pragma unroll
    for (int i = 0; i < 2; i++)
        #pragma unroll
        for (int j = 0; j < 8; j++)
            #pragma unroll
            for (int q = 0; q < 4; q++) acc[i][j][q] = 0.f;

    const int NC = IN_DIM / 32;  // 4

    auto issue = [&](int ck, int p) {
        const int k0 = ck * 32;
        uint32_t a_s = sb + (uint32_t)((Asb[p] - smem) * 4);
        uint32_t b_s = sb + (uint32_t)((Bsb[p] - smem) * 4);
        #pragma unroll
        for (int i = 0; i < 4; i++) {
            int r = i * 32 + lr;
            int rg = bm + r;
            const float* src;
            bool ok = rg < NTOT;
            if (rg < N_USERS)      src = uf + (size_t)rg * IN_DIM + k0 + lc4;
            else if (ok)           src = itf + (size_t)(rg - N_USERS) * IN_DIM + k0 + lc4;
            else                   src = uf;
            cp16(a_s + (uint32_t)(r * PAD + lc4) * 4, src, ok);
        }
        #pragma unroll
        for (int i = 0; i < 4; i++) {
            int r = i * 32 + lr;
            cp16(b_s + (uint32_t)(r * PAD + lc4) * 4,
                 WT + (size_t)r * IN_DIM + k0 + lc4, true);
        }
        cp_commit();
    };

    issue(0, 0);
    for (int ck = 0; ck < NC; ck++) {
        const int p = ck & 1;
        if (ck + 1 < NC) { issue(ck + 1, p ^ 1); cp_wait1(); }
        else             { cp_wait0(); }
        __syncthreads();
        float* As = Asb[p];
        float* Bs = Bsb[p];
        #pragma unroll
        for (int kk = 0; kk < 4; kk++) {
            const int kb = kk * 8;
            uint32_t a[2][4];
            #pragma unroll
            for (int fm = 0; fm < 2; fm++) {
                int r0 = wm + fm * 16 + g;
                a[fm][0] = tf32u(As[r0 * PAD + kb + t]);
                a[fm][1] = tf32u(As[(r0 + 8) * PAD + kb + t]);
                a[fm][2] = tf32u(As[r0 * PAD + kb + t + 4]);
                a[fm][3] = tf32u(As[(r0 + 8) * PAD + kb + t + 4]);
            }
            #pragma unroll
            for (int nf = 0; nf < 8; nf++) {
                uint32_t b[2];
                int rn = wn + nf * 8 + g;
                b[0] = __float_as_uint(Bs[rn * PAD + kb + t]);
                b[1] = __float_as_uint(Bs[rn * PAD + kb + t + 4]);
                mma_tf32(acc[0][nf], a[0], b);
                mma_tf32(acc[1][nf], a[1], b);
            }
        }
        __syncthreads();
    }

    float* dst = (nblk < 2) ? g_x : g_h;
    const bool addb = (nblk < 2);
    const int cbase = (nblk & 1) * 128 + wn;
    #pragma unroll
    for (int fm = 0; fm < 2; fm++) {
        int row = bm + wm + fm * 16 + g;
        #pragma unroll
        for (int nf = 0; nf < 8; nf++) {
            int col = cbase + nf * 8 + 2 * t;
            float bv0 = 0.f, bv1 = 0.f;
            if (addb) { bv0 = __ldg(b0 + col); bv1 = __ldg(b0 + col + 1); }
            if (row < NTOT)
                *(float2*)(dst + (size_t)row * 256 + col) =
                    make_float2(acc[fm][nf][0] + bv0, acc[fm][nf][1] + bv1);
            if (row + 8 < NTOT)
                *(float2*)(dst + (size_t)(row + 8) * 256 + col) =
                    make_float2(acc[fm][nf][2] + bv0, acc[fm][nf][3] + bv1);
        }
    }
}

// ---------------------------------------------------------------------------
// GEMM1 (tf32 mma, cp.async 2-stage): x2 = h_relu @ W1 + b1
// g_h already holds relu'd, tf32-rounded values (fused into spmm1 epilogue),
// so the A fragment path is a pure LDS.
// ---------------------------------------------------------------------------
__global__ __launch_bounds__(256, 2) void gemm1_mma(const float* __restrict__ b1)
{
    extern __shared__ float smem[];
    float* Asb[2] = { smem, smem + TILEF };
    float* Bsb[2] = { smem + 2 * TILEF, smem + 3 * TILEF };
    const uint32_t sb = smem_u32(smem);

    const int tid = threadIdx.x, lane = tid & 31, wid = tid >> 5;
    const int wm = (wid & 3) * 32, wn = (wid >> 2) * 64;
    const int nblk = blockIdx.x;                 // 0..1
    const int bm = blockIdx.y * 128;
    const int g = lane >> 2, t = lane & 3;
    const int lr = tid >> 3;
    const int lc4 = (tid & 7) * 4;

    float acc[2][8][4];
    #pragma unroll
    for (int i = 0; i < 2; i++)
        #pragma unroll
        for (int j = 0; j < 8; j++)
            #pragma unroll
            for (int q = 0; q < 4; q++) acc[i][j][q] = 0.f;

    const int NC = HID / 32;  // 8

    auto issue = [&](int ck, int p) {
        const int k0 = ck * 32;
        uint32_t a_s = sb + (uint32_t)((Asb[p] - smem) * 4);
        uint32_t b_s = sb + (uint32_t)((Bsb[p] - smem) * 4);
        #pragma unroll
        for (int i = 0; i < 4; i++) {
            int r = i * 32 + lr;
            int rg = bm + r;
            bool ok = rg < NTOT;
            const float* src = ok ? g_h + (size_t)rg * HID + k0 + lc4 : g_h;
            cp16(a_s + (uint32_t)(r * PAD + lc4) * 4, src, ok);
        }
        #pragma unroll
        for (int i = 0; i < 4; i++) {
            int r = i * 32 + lr;
            cp16(b_s + (uint32_t)(r * PAD + lc4) * 4,
                 g_W1T + (size_t)(nblk * 128 + r) * HID + k0 + lc4, true);
        }
        cp_commit();
    };

    issue(0, 0);
    for (int ck = 0; ck < NC; ck++) {
        const int p = ck & 1;
        if (ck + 1 < NC) { issue(ck + 1, p ^ 1); cp_wait1(); }
        else             { cp_wait0(); }
        __syncthreads();
        float* As = Asb[p];
        float* Bs = Bsb[p];
        #pragma unroll
        for (int kk = 0; kk < 4; kk++) {
            const int kb = kk * 8;
            uint32_t a[2][4];
            #pragma unroll
            for (int fm = 0; fm < 2; fm++) {
                int r0 = wm + fm * 16 + g;
                a[fm][0] = __float_as_uint(As[r0 * PAD + kb + t]);
                a[fm][1] = __float_as_uint(As[(r0 + 8) * PAD + kb + t]);
                a[fm][2] = __float_as_uint(As[r0 * PAD + kb + t + 4]);
                a[fm][3] = __float_as_uint(As[(r0 + 8) * PAD + kb + t + 4]);
            }
            #pragma unroll
            for (int nf = 0; nf < 8; nf++) {
                uint32_t b[2];
                int rn = wn + nf * 8 + g;
                b[0] = __float_as_uint(Bs[rn * PAD + kb + t]);
                b[1] = __float_as_uint(Bs[rn * PAD + kb + t + 4]);
                mma_tf32(acc[0][nf], a[0], b);
                mma_tf32(acc[1][nf], a[1], b);
            }
        }
        __syncthreads();
    }

    const int cbase = nblk * 128 + wn;
    #pragma unroll
    for (int fm = 0; fm < 2; fm++) {
        int row = bm + wm + fm * 16 + g;
        #pragma unroll
        for (int nf = 0; nf < 8; nf++) {
            int col = cbase + nf * 8 + 2 * t;
            float bv0 = __ldg(b1 + col), bv1 = __ldg(b1 + col + 1);
            if (row < NTOT)
                *(float2*)(g_x2 + (size_t)row * 256 + col) =
                    make_float2(acc[fm][nf][0] + bv0, acc[fm][nf][1] + bv1);
            if (row + 8 < NTOT)
                *(float2*)(g_x2 + (size_t)(row + 8) * 256 + col) =
                    make_float2(acc[fm][nf][2] + bv0, acc[fm][nf][3] + bv1);
        }
    }
}

// ---------------------------------------------------------------------------
// CSR SpMM: warp per row, register accumulation, no atomics.
// MODE 0: g_h = to_tf32(relu(g_h_res + acc))   (layer 0, fused residual+relu)
// MODE 1: Y = acc                               (layer 1, direct out write)
// ---------------------------------------------------------------------------
template <int MODE>
__global__ __launch_bounds__(256) void spmm_csr(
    const float* __restrict__ X, float* __restrict__ Y)
{
    const int row = blockIdx.x * 8 + (threadIdx.x >> 5);
    if (row >= NTOT) return;
    const int lane = threadIdx.x & 31;
    int e = g_rptr[row];
    const int e1 = g_rptr[row + 1];

    float acc[8];
    #pragma unroll
    for (int j = 0; j < 8; j++) acc[j] = 0.f;

    for (; e + 2 <= e1; e += 2) {
        const int   c0 = g_scol[e],     c1 = g_scol[e + 1];
        const float v0 = g_sval[e],     v1 = g_sval[e + 1];
        const float* x0 = X + (size_t)c0 * 256;
        const float* x1 = X + (size_t)c1 * 256;
        #pragma unroll
        for (int j = 0; j < 8; j++) acc[j] += v0 * __ldg(x0 + j * 32 + lane);
        #pragma unroll
        for (int j = 0; j < 8; j++) acc[j] += v1 * __ldg(x1 + j * 32 + lane);
    }
    if (e < e1) {
        const int   c = g_scol[e];
        const float v = g_sval[e];
        const float* xp = X + (size_t)c * 256;
        #pragma unroll
        for (int j = 0; j < 8; j++) acc[j] += v * __ldg(xp + j * 32 + lane);
    }

    float* yp = Y + (size_t)row * 256;
    if (MODE == 0) {
        #pragma unroll
        for (int j = 0; j < 8; j++) {
            float r = yp[j * 32 + lane] + acc[j];
            yp[j * 32 + lane] = to_tf32(fmaxf(r, 0.f));
        }
    } else {
        #pragma unroll
        for (int j = 0; j < 8; j++) yp[j * 32 + lane] = acc[j];
    }
}

// ---------------------------------------------------------------------------
extern "C" void kernel_launch(void* const* d_in, const int* in_sizes, int n_in,
                              void* d_out, int out_size)
{
    const float* user_feat = (const float*)d_in[0];
    const float* item_feat = (const float*)d_in[1];
    const int*   edge_rows = (const int*)  d_in[2];
    const int*   edge_cols = (const int*)  d_in[3];
    const float* edge_vals = (const float*)d_in[4];
    const float* W0        = (const float*)d_in[5];
    const float* b0        = (const float*)d_in[6];
    const float* Wres0     = (const float*)d_in[7];
    const float* W1        = (const float*)d_in[8];
    const float* b1        = (const float*)d_in[9];
    float* out = (float*)d_out;

    float* gx;  cudaGetSymbolAddress((void**)&gx,  g_x);
    float* gh;  cudaGetSymbolAddress((void**)&gh,  g_h);
    float* gx2; cudaGetSymbolAddress((void**)&gx2, g_x2);
    int* rcnt;  cudaGetSymbolAddress((void**)&rcnt,  g_rcnt);
    int* rcnt2; cudaGetSymbolAddress((void**)&rcnt2, g_rcnt2);

    cudaFuncSetAttribute(gemm0_mma, cudaFuncAttributeMaxDynamicSharedMemorySize, G_SMEM);
    cudaFuncSetAttribute(gemm1_mma, cudaFuncAttributeMaxDynamicSharedMemorySize, G_SMEM);

    const int n_mtiles = (NTOT + 127) / 128;
    const int eb = (N_EDGES + 255) / 256;
    const int rb = (NTOT + 7) / 8;   // 12500 blocks, warp per row

    // --- CSR build (reused by both SpMMs) ---
    cudaMemsetAsync(rcnt,  0, NTOT * sizeof(int));
    cudaMemsetAsync(rcnt2, 0, NTOT * sizeof(int));
    row_hist<<<eb, 256>>>(edge_rows);
    row_scan<<<1, 1024>>>();
    edge_scatter<<<eb, 256>>>(edge_rows, edge_cols, edge_vals);

    // weights -> K-major tf32 transposed copies
    transpose_weights<<<(HID * OUT_DIM + 255) / 256, 256>>>(W0, Wres0, W1);

    // Layer 0: x = feat@W0+b0 ; h_res = feat@Wres0
    gemm0_mma<<<dim3(4, n_mtiles), 256, G_SMEM>>>(user_feat, item_feat, b0);

    // g_h = to_tf32(relu(h_res + A@x))   (no atomics, no memset)
    spmm_csr<0><<<rb, 256>>>(gx, gh);

    // Layer 1: x2 = h@W1 + b1
    gemm1_mma<<<dim3(2, n_mtiles), 256, G_SMEM>>>(b1);

    // out = A @ x2   (direct write)
    spmm_csr<1><<<rb, 256>>>(gx2, out);
}

// round 8
// speedup vs baseline: 2.0646x; 1.1372x over previous
#include <cuda_runtime.h>
#include <cstdint>

#define N_USERS  40000
#define NTOT     100000
#define IN_DIM   128
#define HID      256
#define OUT_DIM  256
#define N_EDGES  600000

// Scratch (allocation-free rule: device globals)
__device__ float g_P  [(size_t)NTOT * IN_DIM];  // A @ feat
__device__ float g_h  [(size_t)NTOT * HID];     // relu([P|F]@[W0;Wres] + rowsum*b0)
__device__ float g_x2 [(size_t)NTOT * OUT_DIM]; // h @ W1 + b1
__device__ float g_rsum[NTOT];                  // A @ 1
__device__ float g_WhT[HID * 256];              // [n][k]: k<128 -> W0[k][n], else Wres[k-128][n]
__device__ float g_W1T[OUT_DIM * HID];          // W1^T, tf32
__device__ int   g_rcnt [NTOT];
__device__ int   g_rcnt2[NTOT];
__device__ int   g_rptr [NTOT + 1];
__device__ int   g_scol[N_EDGES];
__device__ float g_sval[N_EDGES];

__device__ __forceinline__ float to_tf32(float x) {
    uint32_t u;
    asm("cvt.rna.tf32.f32 %0, %1;" : "=r"(u) : "f"(x));
    return __uint_as_float(u);
}
__device__ __forceinline__ uint32_t tf32u(float x) {
    uint32_t u;
    asm("cvt.rna.tf32.f32 %0, %1;" : "=r"(u) : "f"(x));
    return u;
}
__device__ __forceinline__ void mma_tf32(float* c, const uint32_t* a, const uint32_t* b) {
    asm volatile(
        "mma.sync.aligned.m16n8k8.row.col.f32.tf32.tf32.f32 "
        "{%0,%1,%2,%3}, {%4,%5,%6,%7}, {%8,%9}, {%0,%1,%2,%3};"
        : "+f"(c[0]), "+f"(c[1]), "+f"(c[2]), "+f"(c[3])
        : "r"(a[0]), "r"(a[1]), "r"(a[2]), "r"(a[3]), "r"(b[0]), "r"(b[1]));
}
__device__ __forceinline__ uint32_t smem_u32(const void* p) {
    uint32_t a;
    asm("{ .reg .u64 t; cvta.to.shared.u64 t, %1; cvt.u32.u64 %0, t; }" : "=r"(a) : "l"(p));
    return a;
}
__device__ __forceinline__ void cp16(uint32_t dst, const void* src, bool pred) {
    int sz = pred ? 16 : 0;
    asm volatile("cp.async.ca.shared.global [%0], [%1], 16, %2;"
                 :: "r"(dst), "l"(src), "r"(sz) : "memory");
}
__device__ __forceinline__ void cp_commit() {
    asm volatile("cp.async.commit_group;" ::: "memory");
}
__device__ __forceinline__ void cp_wait1() {
    asm volatile("cp.async.wait_group 1;" ::: "memory");
}
__device__ __forceinline__ void cp_wait0() {
    asm volatile("cp.async.wait_group 0;" ::: "memory");
}

#define PAD 36
#define TILEF (128 * PAD)
#define G_SMEM (4 * TILEF * 4)   // 73728 B

// ---------------------------------------------------------------------------
// Weight prep: g_WhT[n][k] = tf32( k<128 ? W0[k][n] : Wres[k-128][n] ),
//              g_W1T[n][k] = tf32( W1[k][n] )
// ---------------------------------------------------------------------------
__global__ void transpose_weights(const float* __restrict__ W0,
                                  const float* __restrict__ Wres,
                                  const float* __restrict__ W1) {
    int idx = blockIdx.x * 256 + threadIdx.x;
    if (idx < IN_DIM * HID) {      // k in [0,128), n in [0,256)
        int k = idx / HID, n = idx % HID;
        g_WhT[n * 256 + k]       = to_tf32(W0[idx]);
        g_WhT[n * 256 + 128 + k] = to_tf32(Wres[idx]);
    }
    if (idx < HID * OUT_DIM) {
        int k = idx / OUT_DIM, n = idx % OUT_DIM;
        g_W1T[n * HID + k] = to_tf32(W1[idx]);
    }
}

// ---------------------------------------------------------------------------
// CSR build: per-row histogram -> 1-block chunked exclusive scan -> scatter
// ---------------------------------------------------------------------------
__global__ __launch_bounds__(256) void row_hist(const int* __restrict__ rows) {
    int e = blockIdx.x * 256 + threadIdx.x;
    if (e < N_EDGES) atomicAdd(&g_rcnt[rows[e]], 1);
}

#define CHUNK 98
__global__ __launch_bounds__(1024) void row_scan() {
    __shared__ int ssum[1024];
    const int tid = threadIdx.x;
    const int base = tid * CHUNK;
    int s = 0;
    #pragma unroll 7
    for (int i = 0; i < CHUNK; i++) {
        int idx = base + i;
        if (idx < NTOT) s += g_rcnt[idx];
    }
    ssum[tid] = s;
    __syncthreads();
    for (int d = 1; d < 1024; d <<= 1) {
        int o = (tid >= d) ? ssum[tid - d] : 0;
        __syncthreads();
        ssum[tid] += o;
        __syncthreads();
    }
    int run = ssum[tid] - s;
    #pragma unroll 7
    for (int i = 0; i < CHUNK; i++) {
        int idx = base + i;
        if (idx < NTOT) {
            g_rptr[idx] = run;
            run += g_rcnt[idx];
        }
    }
    if (tid == 1023) g_rptr[NTOT] = ssum[1023];
}

__global__ __launch_bounds__(256) void edge_scatter(
    const int* __restrict__ rows, const int* __restrict__ cols,
    const float* __restrict__ vals) {
    int e = blockIdx.x * 256 + threadIdx.x;
    if (e >= N_EDGES) return;
    int r = rows[e];
    int pos = g_rptr[r] + atomicAdd(&g_rcnt2[r], 1);
    g_scol[pos] = cols[e];
    g_sval[pos] = vals[e];
}

// ---------------------------------------------------------------------------
// spmmP: P = A @ feat (128 cols, 4 floats/lane), rowsum = A @ 1
// feat is 51 MB -> L2-resident gather. Warp per row, no atomics.
// ---------------------------------------------------------------------------
__global__ __launch_bounds__(256) void spmm_feat(
    const float* __restrict__ uf, const float* __restrict__ itf)
{
    const int row = blockIdx.x * 8 + (threadIdx.x >> 5);
    if (row >= NTOT) return;
    const int lane = threadIdx.x & 31;
    int e = g_rptr[row];
    const int e1 = g_rptr[row + 1];

    float acc[4] = {0.f, 0.f, 0.f, 0.f};
    float rs = 0.f;

    for (; e + 2 <= e1; e += 2) {
        const int c0 = g_scol[e], c1 = g_scol[e + 1];
        const float v0 = g_sval[e], v1 = g_sval[e + 1];
        const float* x0 = (c0 < N_USERS) ? uf + (size_t)c0 * IN_DIM
                                         : itf + (size_t)(c0 - N_USERS) * IN_DIM;
        const float* x1 = (c1 < N_USERS) ? uf + (size_t)c1 * IN_DIM
                                         : itf + (size_t)(c1 - N_USERS) * IN_DIM;
        #pragma unroll
        for (int j = 0; j < 4; j++) acc[j] += v0 * __ldg(x0 + j * 32 + lane);
        #pragma unroll
        for (int j = 0; j < 4; j++) acc[j] += v1 * __ldg(x1 + j * 32 + lane);
        rs += v0 + v1;
    }
    if (e < e1) {
        const int c = g_scol[e];
        const float v = g_sval[e];
        const float* xp = (c < N_USERS) ? uf + (size_t)c * IN_DIM
                                        : itf + (size_t)(c - N_USERS) * IN_DIM;
        #pragma unroll
        for (int j = 0; j < 4; j++) acc[j] += v * __ldg(xp + j * 32 + lane);
        rs += v;
    }

    float* pp = g_P + (size_t)row * IN_DIM;
    #pragma unroll
    for (int j = 0; j < 4; j++) pp[j * 32 + lane] = acc[j];
    if (lane == 0) g_rsum[row] = rs;
}

// ---------------------------------------------------------------------------
// gemm_h (tf32 mma, cp.async 2-stage): h = relu([P|F] @ WhT + rowsum*b0)
// K=256: chunks 0..3 from P, 4..7 from feat. tf32-round h for storage.
// ---------------------------------------------------------------------------
__global__ __launch_bounds__(256, 2) void gemmh_mma(
    const float* __restrict__ uf, const float* __restrict__ itf,
    const float* __restrict__ b0)
{
    extern __shared__ float smem[];
    float* Asb[2] = { smem, smem + TILEF };
    float* Bsb[2] = { smem + 2 * TILEF, smem + 3 * TILEF };
    const uint32_t sb = smem_u32(smem);

    const int tid = threadIdx.x, lane = tid & 31, wid = tid >> 5;
    const int wm = (wid & 3) * 32, wn = (wid >> 2) * 64;
    const int nblk = blockIdx.x;                 // 0..1
    const int bm = blockIdx.y * 128;
    const int g = lane >> 2, t = lane & 3;
    const int lr = tid >> 3;
    const int lc4 = (tid & 7) * 4;

    float acc[2][8][4];
    #pragma unroll
    for (int i = 0; i < 2; i++)
        #pragma unroll
        for (int j = 0; j < 8; j++)
            #pragma unroll
            for (int q = 0; q < 4; q++) acc[i][j][q] = 0.f;

    const int NC = 8;

    auto issue = [&](int ck, int p) {
        uint32_t a_s = sb + (uint32_t)((Asb[p] - smem) * 4);
        uint32_t b_s = sb + (uint32_t)((Bsb[p] - smem) * 4);
        #pragma unroll
        for (int i = 0; i < 4; i++) {
            int r = i * 32 + lr;
            int rg = bm + r;
            bool ok = rg < NTOT;
            const float* src;
            if (ck < 4) {
                src = ok ? g_P + (size_t)rg * IN_DIM + ck * 32 + lc4 : g_P;
            } else {
                int kf = (ck - 4) * 32 + lc4;
                if (rg < N_USERS)      src = uf + (size_t)rg * IN_DIM + kf;
                else if (ok)           src = itf + (size_t)(rg - N_USERS) * IN_DIM + kf;
                else                   src = uf;
            }
            cp16(a_s + (uint32_t)(r * PAD + lc4) * 4, src, ok);
        }
        #pragma unroll
        for (int i = 0; i < 4; i++) {
            int r = i * 32 + lr;
            cp16(b_s + (uint32_t)(r * PAD + lc4) * 4,
                 g_WhT + (size_t)(nblk * 128 + r) * 256 + ck * 32 + lc4, true);
        }
        cp_commit();
    };

    issue(0, 0);
    for (int ck = 0; ck < NC; ck++) {
        const int p = ck & 1;
        if (ck + 1 < NC) { issue(ck + 1, p ^ 1); cp_wait1(); }
        else             { cp_wait0(); }
        __syncthreads();
        float* As = Asb[p];
        float* Bs = Bsb[p];
        #pragma unroll
        for (int kk = 0; kk < 4; kk++) {
            const int kb = kk * 8;
            uint32_t a[2][4];
            #pragma unroll
            for (int fm = 0; fm < 2; fm++) {
                int r0 = wm + fm * 16 + g;
                a[fm][0] = tf32u(As[r0 * PAD + kb + t]);
                a[fm][1] = tf32u(As[(r0 + 8) * PAD + kb + t]);
                a[fm][2] = tf32u(As[r0 * PAD + kb + t + 4]);
                a[fm][3] = tf32u(As[(r0 + 8) * PAD + kb + t + 4]);
            }
            #pragma unroll
            for (int nf = 0; nf < 8; nf++) {
                uint32_t b[2];
                int rn = wn + nf * 8 + g;
                b[0] = __float_as_uint(Bs[rn * PAD + kb + t]);
                b[1] = __float_as_uint(Bs[rn * PAD + kb + t + 4]);
                mma_tf32(acc[0][nf], a[0], b);
                mma_tf32(acc[1][nf], a[1], b);
            }
        }
        __syncthreads();
    }

    const int cbase = nblk * 128 + wn;
    #pragma unroll
    for (int fm = 0; fm < 2; fm++) {
        int row = bm + wm + fm * 16 + g;
        float rs0 = (row < NTOT)     ? __ldg(g_rsum + row)     : 0.f;
        float rs1 = (row + 8 < NTOT) ? __ldg(g_rsum + row + 8) : 0.f;
        #pragma unroll
        for (int nf = 0; nf < 8; nf++) {
            int col = cbase + nf * 8 + 2 * t;
            float bv0 = __ldg(b0 + col), bv1 = __ldg(b0 + col + 1);
            if (row < NTOT) {
                float o0 = to_tf32(fmaxf(acc[fm][nf][0] + rs0 * bv0, 0.f));
                float o1 = to_tf32(fmaxf(acc[fm][nf][1] + rs0 * bv1, 0.f));
                *(float2*)(g_h + (size_t)row * 256 + col) = make_float2(o0, o1);
            }
            if (row + 8 < NTOT) {
                float o2 = to_tf32(fmaxf(acc[fm][nf][2] + rs1 * bv0, 0.f));
                float o3 = to_tf32(fmaxf(acc[fm][nf][3] + rs1 * bv1, 0.f));
                *(float2*)(g_h + (size_t)(row + 8) * 256 + col) = make_float2(o2, o3);
            }
        }
    }
}

// ---------------------------------------------------------------------------
// GEMM1 (tf32 mma, cp.async 2-stage): x2 = h @ W1 + b1 (h pre-rounded -> pure LDS)
// ---------------------------------------------------------------------------
__global__ __launch_bounds__(256, 2) void gemm1_mma(const float* __restrict__ b1)
{
    extern __shared__ float smem[];
    float* Asb[2] = { smem, smem + TILEF };
    float* Bsb[2] = { smem + 2 * TILEF, smem + 3 * TILEF };
    const uint32_t sb = smem_u32(smem);

    const int tid = threadIdx.x, lane = tid & 31, wid = tid >> 5;
    const int wm = (wid & 3) * 32, wn = (wid >> 2) * 64;
    const int nblk = blockIdx.x;                 // 0..1
    const int bm = blockIdx.y * 128;
    const int g = lane >> 2, t = lane & 3;
    const int lr = tid >> 3;
    const int lc4 = (tid & 7) * 4;

    float acc[2][8][4];
    #pragma unroll
    for (int i = 0; i < 2; i++)
        #pragma unroll
        for (int j = 0; j < 8; j++)
            #pragma unroll
            for (int q = 0; q < 4; q++) acc[i][j][q] = 0.f;

    const int NC = HID / 32;  // 8

    auto issue = [&](int ck, int p) {
        const int k0 = ck * 32;
        uint32_t a_s = sb + (uint32_t)((Asb[p] - smem) * 4);
        uint32_t b_s = sb + (uint32_t)((Bsb[p] - smem) * 4);
        #pragma unroll
        for (int i = 0; i < 4; i++) {
            int r = i * 32 + lr;
            int rg = bm + r;
            bool ok = rg < NTOT;
            const float* src = ok ? g_h + (size_t)rg * HID + k0 + lc4 : g_h;
            cp16(a_s + (uint32_t)(r * PAD + lc4) * 4, src, ok);
        }
        #pragma unroll
        for (int i = 0; i < 4; i++) {
            int r = i * 32 + lr;
            cp16(b_s + (uint32_t)(r * PAD + lc4) * 4,
                 g_W1T + (size_t)(nblk * 128 + r) * HID + k0 + lc4, true);
        }
        cp_commit();
    };

    issue(0, 0);
    for (int ck = 0; ck < NC; ck++) {
        const int p = ck & 1;
        if (ck + 1 < NC) { issue(ck + 1, p ^ 1); cp_wait1(); }
        else             { cp_wait0(); }
        __syncthreads();
        float* As = Asb[p];
        float* Bs = Bsb[p];
        #pragma unroll
        for (int kk = 0; kk < 4; kk++) {
            const int kb = kk * 8;
            uint32_t a[2][4];
            #pragma unroll
            for (int fm = 0; fm < 2; fm++) {
                int r0 = wm + fm * 16 + g;
                a[fm][0] = __float_as_uint(As[r0 * PAD + kb + t]);
                a[fm][1] = __float_as_uint(As[(r0 + 8) * PAD + kb + t]);
                a[fm][2] = __float_as_uint(As[r0 * PAD + kb + t + 4]);
                a[fm][3] = __float_as_uint(As[(r0 + 8) * PAD + kb + t + 4]);
            }
            #pragma unroll
            for (int nf = 0; nf < 8; nf++) {
                uint32_t b[2];
                int rn = wn + nf * 8 + g;
                b[0] = __float_as_uint(Bs[rn * PAD + kb + t]);
                b[1] = __float_as_uint(Bs[rn * PAD + kb + t + 4]);
                mma_tf32(acc[0][nf], a[0], b);
                mma_tf32(acc[1][nf], a[1], b);
            }
        }
        __syncthreads();
    }

    const int cbase = nblk * 128 + wn;
    #pragma unroll
    for (int fm = 0; fm < 2; fm++) {
        int row = bm + wm + fm * 16 + g;
        #pragma unroll
        for (int nf = 0; nf < 8; nf++) {
            int col = cbase + nf * 8 + 2 * t;
            float bv0 = __ldg(b1 + col), bv1 = __ldg(b1 + col + 1);
            if (row < NTOT)
                *(float2*)(g_x2 + (size_t)row * 256 + col) =
                    make_float2(acc[fm][nf][0] + bv0, acc[fm][nf][1] + bv1);
            if (row + 8 < NTOT)
                *(float2*)(g_x2 + (size_t)(row + 8) * 256 + col) =
                    make_float2(acc[fm][nf][2] + bv0, acc[fm][nf][3] + bv1);
        }
    }
}

// ---------------------------------------------------------------------------
// CSR SpMM (256 cols): out = A @ x2, warp per row, direct write, no atomics.
// ---------------------------------------------------------------------------
__global__ __launch_bounds__(256) void spmm_csr(
    const float* __restrict__ X, float* __restrict__ Y)
{
    const int row = blockIdx.x * 8 + (threadIdx.x >> 5);
    if (row >= NTOT) return;
    const int lane = threadIdx.x & 31;
    int e = g_rptr[row];
    const int e1 = g_rptr[row + 1];

    float acc[8];
    #pragma unroll
    for (int j = 0; j < 8; j++) acc[j] = 0.f;

    for (; e + 2 <= e1; e += 2) {
        const int   c0 = g_scol[e],     c1 = g_scol[e + 1];
        const float v0 = g_sval[e],     v1 = g_sval[e + 1];
        const float* x0 = X + (size_t)c0 * 256;
        const float* x1 = X + (size_t)c1 * 256;
        #pragma unroll
        for (int j = 0; j < 8; j++) acc[j] += v0 * __ldg(x0 + j * 32 + lane);
        #pragma unroll
        for (int j = 0; j < 8; j++) acc[j] += v1 * __ldg(x1 + j * 32 + lane);
    }
    if (e < e1) {
        const int   c = g_scol[e];
        const float v = g_sval[e];
        const float* xp = X + (size_t)c * 256;
        #pragma unroll
        for (int j = 0; j < 8; j++) acc[j] += v * __ldg(xp + j * 32 + lane);
    }

    float* yp = Y + (size_t)row * 256;
    #pragma unroll
    for (int j = 0; j < 8; j++) yp[j * 32 + lane] = acc[j];
}

// ---------------------------------------------------------------------------
extern "C" void kernel_launch(void* const* d_in, const int* in_sizes, int n_in,
                              void* d_out, int out_size)
{
    const float* user_feat = (const float*)d_in[0];
    const float* item_feat = (const float*)d_in[1];
    const int*   edge_rows = (const int*)  d_in[2];
    const int*   edge_cols = (const int*)  d_in[3];
    const float* edge_vals = (const float*)d_in[4];
    const float* W0        = (const float*)d_in[5];
    const float* b0        = (const float*)d_in[6];
    const float* Wres0     = (const float*)d_in[7];
    const float* W1        = (const float*)d_in[8];
    const float* b1        = (const float*)d_in[9];
    float* out = (float*)d_out;

    float* gx2; cudaGetSymbolAddress((void**)&gx2, g_x2);
    int* rcnt;  cudaGetSymbolAddress((void**)&rcnt,  g_rcnt);
    int* rcnt2; cudaGetSymbolAddress((void**)&rcnt2, g_rcnt2);

    cudaFuncSetAttribute(gemmh_mma, cudaFuncAttributeMaxDynamicSharedMemorySize, G_SMEM);
    cudaFuncSetAttribute(gemm1_mma, cudaFuncAttributeMaxDynamicSharedMemorySize, G_SMEM);

    const int n_mtiles = (NTOT + 127) / 128;
    const int eb = (N_EDGES + 255) / 256;
    const int rb = (NTOT + 7) / 8;

    // --- CSR build (reused by both SpMMs) ---
    cudaMemsetAsync(rcnt,  0, NTOT * sizeof(int));
    cudaMemsetAsync(rcnt2, 0, NTOT * sizeof(int));
    row_hist<<<eb, 256>>>(edge_rows);
    row_scan<<<1, 1024>>>();
    edge_scatter<<<eb, 256>>>(edge_rows, edge_cols, edge_vals);

    // weights -> fused/transposed tf32 copies
    transpose_weights<<<(HID * OUT_DIM + 255) / 256, 256>>>(W0, Wres0, W1);

    // P = A @ feat, rowsum = A @ 1   (feat gather is L2-resident)
    spmm_feat<<<rb, 256>>>(user_feat, item_feat);

    // h = relu(P@W0 + feat@Wres + rowsum*b0)   (single K=256 GEMM)
    gemmh_mma<<<dim3(2, n_mtiles), 256, G_SMEM>>>(user_feat, item_feat, b0);

    // x2 = h @ W1 + b1
    gemm1_mma<<<dim3(2, n_mtiles), 256, G_SMEM>>>(b1);

    // out = A @ x2
    spmm_csr<<<rb, 256>>>(gx2, out);
}